// round 2
// baseline (speedup 1.0000x reference)
#include <cuda_runtime.h>

typedef unsigned long long ull;

// Problem constants: B=2, N=1024, T=64, H=64
#define NN 1024
#define HH 64

// Scratch (allocation-free rule: __device__ globals)
// layout [b][h][n] so kernel2 tile loads are coalesced
__device__ float g_p[2 * HH * NN];
__device__ float g_q[2 * HH * NN];
__device__ float g_U[NN];
__device__ float g_V[NN];
__device__ float g_wq[2 * HH];   // duplicated packed 0.2475*W2[h] pairs

// ---- packed f32x2 helpers (Blackwell FFMA2 path) ----
__device__ __forceinline__ ull add_f32x2(ull a, ull b) {
    ull d; asm("add.rn.f32x2 %0, %1, %2;" : "=l"(d) : "l"(a), "l"(b)); return d;
}
__device__ __forceinline__ ull fma_f32x2(ull a, ull b, ull c) {
    ull d; asm("fma.rn.f32x2 %0, %1, %2, %3;" : "=l"(d) : "l"(a), "l"(b), "l"(c)); return d;
}

// ---------------------------------------------------------------------------
// Kernel 1: per-node projections. 128 blocks x 256 threads, 8 nodes/block.
//   p[b,h,n] = sum_t x[b,n,t]*W1[h,t]
//   q[b,h,n] = sum_t x[b,n,t]*W1[h,64+t] + b1[h]
//   U[n] = 0.2525*sum_{b,h} w2[h]*p ;  V[n] = 0.2525*sum_{b,h} w2[h]*q + b2
// ---------------------------------------------------------------------------
__global__ void __launch_bounds__(256) k1_proj(
    const float* __restrict__ x, const float* __restrict__ W1,
    const float* __restrict__ b1, const float* __restrict__ W2,
    const float* __restrict__ b2) {
    __shared__ float sW[64][129];      // [h][t2], pitch 129 -> conflict-free
    __shared__ float sx[2][8][64];
    __shared__ float sbuf[1152];       // multi-use: reduction then staging

    const int tid = threadIdx.x;
    const int n0 = blockIdx.x * 8;
    const int h = tid & 63;
    const int s = tid >> 6;            // 0..3

    // pack w for k2 (block 0 only)
    if (blockIdx.x == 0 && tid < 64) {
        float w = 0.2475f * W2[tid];
        g_wq[2 * tid] = w; g_wq[2 * tid + 1] = w;
    }

    // W1 [64][128] -> sW[h][t2], coalesced
    #pragma unroll
    for (int k = 0; k < 32; ++k) {
        int l = k * 256 + tid;
        sW[l >> 7][l & 127] = W1[l];
    }
    // x rows for 8 nodes, both batches
    #pragma unroll
    for (int k = 0; k < 4; ++k) {
        int l = k * 256 + tid;              // 0..1023
        int b = l >> 9, node = (l >> 6) & 7, t = l & 63;
        sx[b][node][t] = x[((b << 10) + n0 + node) * 64 + t];
    }
    __syncthreads();

    float p[2][2], q[2][2];
    #pragma unroll
    for (int b = 0; b < 2; ++b)
        #pragma unroll
        for (int g = 0; g < 2; ++g) { p[b][g] = 0.f; q[b][g] = 0.f; }

    #pragma unroll 8
    for (int t = 0; t < 64; ++t) {
        float wa = sW[h][t];
        float wb = sW[h][64 + t];
        #pragma unroll
        for (int b = 0; b < 2; ++b)
            #pragma unroll
            for (int g = 0; g < 2; ++g) {
                float xv = sx[b][s * 2 + g][t];
                p[b][g] = fmaf(xv, wa, p[b][g]);
                q[b][g] = fmaf(xv, wb, q[b][g]);
            }
    }
    float bb = b1[h];
    #pragma unroll
    for (int b = 0; b < 2; ++b)
        #pragma unroll
        for (int g = 0; g < 2; ++g) q[b][g] += bb;

    // U/V reduction: pitch-66 scratch (conflict-free for the 16 reducers)
    {
        float w2h = W2[h];
        #pragma unroll
        for (int g = 0; g < 2; ++g) {
            int n = s * 2 + g;
            sbuf[n * 66 + h]       = w2h * (p[0][g] + p[1][g]);
            sbuf[528 + n * 66 + h] = w2h * (q[0][g] + q[1][g]);
        }
    }
    __syncthreads();
    if (tid < 16) {
        int n = tid >> 1, sel = tid & 1;
        const float* base = sbuf + sel * 528 + n * 66;
        float acc = 0.f;
        #pragma unroll 8
        for (int hh = 0; hh < 64; ++hh) acc += base[hh];
        if (sel == 0) g_U[n0 + n] = 0.2525f * acc;
        else          g_V[n0 + n] = 0.2525f * acc + b2[0];
    }
    __syncthreads();

    // stage p (pitch 9) then coalesced store
    #pragma unroll
    for (int b = 0; b < 2; ++b)
        #pragma unroll
        for (int g = 0; g < 2; ++g)
            sbuf[(b * 64 + h) * 9 + s * 2 + g] = p[b][g];
    __syncthreads();
    #pragma unroll
    for (int k = 0; k < 4; ++k) {
        int l = k * 256 + tid;
        int node = l & 7, hh = (l >> 3) & 63, b = l >> 9;
        g_p[((b << 6) | hh) * 1024 + n0 + node] = sbuf[((b << 6) | hh) * 9 + node];
    }
    __syncthreads();
    // stage q
    #pragma unroll
    for (int b = 0; b < 2; ++b)
        #pragma unroll
        for (int g = 0; g < 2; ++g)
            sbuf[(b * 64 + h) * 9 + s * 2 + g] = q[b][g];
    __syncthreads();
    #pragma unroll
    for (int k = 0; k < 4; ++k) {
        int l = k * 256 + tid;
        int node = l & 7, hh = (l >> 3) & 63, b = l >> 9;
        g_q[((b << 6) | hh) * 1024 + n0 + node] = sbuf[((b << 6) | hh) * 9 + node];
    }
}

// ---------------------------------------------------------------------------
// Kernel 2: pairwise |z| accumulation via packed f32x2.
//   out[i,j] = sum_{b,h} 0.2475*w2[h]*|p[b,i,h]+q[b,j,h]| + U[i] + V[j]
// Grid 16x16, block 16x16 threads, 4x4 register tile (packed along i-pairs).
// smem: ps[64][64] (16KB) + qsd[64][128] duplicated pairs (32KB) = 48KB.
// ---------------------------------------------------------------------------
__global__ void __launch_bounds__(256) k2_pair(float* __restrict__ out) {
    __shared__ __align__(16) float ps[64][64];     // [h][i]
    __shared__ __align__(16) float qsd[64][128];   // [h][2j] duplicated

    const int tx = threadIdx.x, ty = threadIdx.y;
    const int tid = ty * 16 + tx;
    const int i0 = blockIdx.y * 64, j0 = blockIdx.x * 64;
    const ull MASK = 0x7FFFFFFF7FFFFFFFULL;

    ull acc[2][4];
    #pragma unroll
    for (int r = 0; r < 2; ++r)
        #pragma unroll
        for (int c = 0; c < 4; ++c) acc[r][c] = 0ULL;

    #pragma unroll
    for (int b = 0; b < 2; ++b) {
        const float* pg = g_p + b * 64 * 1024;
        const float* qg = g_q + b * 64 * 1024;
        __syncthreads();
        #pragma unroll
        for (int k = 0; k < 4; ++k) {           // ps fill: float4 coalesced
            int l = k * 256 + tid;              // 0..1023 float4 idx
            int hh = l >> 4, io = (l & 15) << 2;
            *(float4*)&ps[hh][io] = *(const float4*)&pg[hh * 1024 + i0 + io];
        }
        #pragma unroll
        for (int k = 0; k < 16; ++k) {          // qsd fill: duplicate pairs
            int l = k * 256 + tid;              // 0..4095
            int hh = l >> 6, j = l & 63;
            float v = qg[hh * 1024 + j0 + j];
            float2 d = make_float2(v, v);
            *(float2*)&qsd[hh][2 * j] = d;
        }
        __syncthreads();

        #pragma unroll 8
        for (int h = 0; h < 64; ++h) {
            ull wq = __ldg((const ull*)(g_wq + 2 * h));
            ulonglong2 ppv = *(const ulonglong2*)&ps[h][ty << 2];   // (p0,p1),(p2,p3)
            ulonglong2 qA  = *(const ulonglong2*)&qsd[h][tx << 3];  // (q0,q0),(q1,q1)
            ulonglong2 qB  = *(const ulonglong2*)&qsd[h][(tx << 3) + 4];
            ull pr[2] = {ppv.x, ppv.y};
            ull qc[4] = {qA.x, qA.y, qB.x, qB.y};
            #pragma unroll
            for (int r = 0; r < 2; ++r)
                #pragma unroll
                for (int c = 0; c < 4; ++c) {
                    ull z = add_f32x2(pr[r], qc[c]);
                    z &= MASK;                                      // packed |z|
                    acc[r][c] = fma_f32x2(wq, z, acc[r][c]);
                }
        }
    }

    float u[4], v[4];
    #pragma unroll
    for (int r = 0; r < 4; ++r) u[r] = g_U[i0 + (ty << 2) + r];
    #pragma unroll
    for (int c = 0; c < 4; ++c) v[c] = g_V[j0 + (tx << 2) + c];

    #pragma unroll
    for (int r2 = 0; r2 < 2; ++r2) {
        float2 a0 = *(float2*)&acc[r2][0];
        float2 a1 = *(float2*)&acc[r2][1];
        float2 a2 = *(float2*)&acc[r2][2];
        float2 a3 = *(float2*)&acc[r2][3];
        int rA = (ty << 2) + r2 * 2, rB = rA + 1;
        float4 oA, oB;
        oA.x = a0.x + u[r2 * 2] + v[0]; oB.x = a0.y + u[r2 * 2 + 1] + v[0];
        oA.y = a1.x + u[r2 * 2] + v[1]; oB.y = a1.y + u[r2 * 2 + 1] + v[1];
        oA.z = a2.x + u[r2 * 2] + v[2]; oB.z = a2.y + u[r2 * 2 + 1] + v[2];
        oA.w = a3.x + u[r2 * 2] + v[3]; oB.w = a3.y + u[r2 * 2 + 1] + v[3];
        *(float4*)&out[(i0 + rA) * 1024 + j0 + (tx << 2)] = oA;
        *(float4*)&out[(i0 + rB) * 1024 + j0 + (tx << 2)] = oB;
    }
}

// ---------------------------------------------------------------------------
// Kernel 3: per-row gumbel + argmax -> one-hot (straight-through == hard)
// ---------------------------------------------------------------------------
__global__ void __launch_bounds__(256) k3_argmax(const float* __restrict__ gu,
                                                 float* __restrict__ out) {
    __shared__ float sv[256];
    __shared__ int si[256];
    const int i = blockIdx.x, tid = threadIdx.x;

    float best = -3.0e38f;
    int bj = 1 << 30;
    #pragma unroll
    for (int k = 0; k < 4; ++k) {
        int j = k * 256 + tid;
        float u = gu[i * 1024 + j];
        float g = -__logf(-__logf(u + 1e-10f) + 1e-10f);
        float v = out[i * 1024 + j] + g;
        if (v > best || (v == best && j < bj)) { best = v; bj = j; }
    }
    sv[tid] = best; si[tid] = bj;
    __syncthreads();
    for (int s = 128; s > 0; s >>= 1) {
        if (tid < s) {
            float v2 = sv[tid + s]; int j2 = si[tid + s];
            if (v2 > sv[tid] || (v2 == sv[tid] && j2 < si[tid])) {
                sv[tid] = v2; si[tid] = j2;
            }
        }
        __syncthreads();
    }
    const int arg = si[0];
    #pragma unroll
    for (int k = 0; k < 4; ++k) {
        int j = k * 256 + tid;
        out[i * 1024 + j] = (j == arg) ? 1.0f : 0.0f;
    }
}

// ---------------------------------------------------------------------------
extern "C" void kernel_launch(void* const* d_in, const int* in_sizes, int n_in,
                              void* d_out, int out_size) {
    const float* x  = (const float*)d_in[0];   // [2,1024,64]
    const float* W1 = (const float*)d_in[1];   // [64,128]
    const float* b1 = (const float*)d_in[2];   // [64]
    const float* W2 = (const float*)d_in[3];   // [1,64]
    const float* b2 = (const float*)d_in[4];   // [1]
    const float* gu = (const float*)d_in[5];   // [1024,1024]
    float* out = (float*)d_out;                // [1024,1024] fp32

    k1_proj<<<128, 256>>>(x, W1, b1, W2, b2);
    k2_pair<<<dim3(16, 16), dim3(16, 16)>>>(out);
    k3_argmax<<<1024, 256>>>(gu, out);
}